// round 15
// baseline (speedup 1.0000x reference)
#include <cuda_runtime.h>
#include <cuda_bf16.h>
#include <cstdint>
#include <cstddef>

#define BB 4096
#define LL 50
#define NN 50
#define DD 128
#define PK 136                    // padded row stride (elements) -> 272B = 17*16: LDSM-aligned, conflict-free
#define TILE4 2176                // float4s per bf16 tile image (128*PK*2/16)
#define TPB 512

// ---- main-kernel smem layout (byte offsets) ----
#define A_HI  0
#define A_LO  34816
#define AUX   69632
#define AUX_CNT   (AUX + 0)       // int[4][64]
#define AUX_WA    (AUX + 1024)    // float[128]
#define AUX_VNP   (AUX + 1536)    // float[4][128]
#define AUX_ALPHA (AUX + 3584)    // float[4][64]
#define AUX_PART  (AUX + 4608)    // float[128][8]
#define SMEM_TOTAL (AUX + 8704)   // 78336  -> 2 CTAs/SM

__device__ float g_vnp[BB * DD];
// Fragment-major B table: idx = p*2048 + ks*256 + wn*32 + lane (p: 0=hi,1=lo)
// uint4 = {b0_nt0, b1_nt0, b0_nt1, b1_nt1} for mma.m16n8k16
__device__ __align__(16) uint4 g_fragB[4096];   // 64 KB

__device__ __forceinline__ uint32_t smem_u32(const void* p) {
    uint32_t a;
    asm("{ .reg .u64 t; cvta.to.shared.u64 t, %1; cvt.u32.u64 %0, t; }" : "=r"(a) : "l"(p));
    return a;
}
__device__ __forceinline__ void ldsm_x4(uint32_t& r0, uint32_t& r1, uint32_t& r2, uint32_t& r3, uint32_t addr) {
    asm volatile("ldmatrix.sync.aligned.m8n8.x4.shared.b16 {%0,%1,%2,%3}, [%4];"
                 : "=r"(r0), "=r"(r1), "=r"(r2), "=r"(r3) : "r"(addr));
}
__device__ __forceinline__ void mma_bf16(float* d, uint32_t a0, uint32_t a1, uint32_t a2, uint32_t a3,
                                         uint32_t b0, uint32_t b1) {
    asm volatile("mma.sync.aligned.m16n8k16.row.col.f32.bf16.bf16.f32 "
                 "{%0,%1,%2,%3}, {%4,%5,%6,%7}, {%8,%9}, {%0,%1,%2,%3};"
                 : "+f"(d[0]), "+f"(d[1]), "+f"(d[2]), "+f"(d[3])
                 : "r"(a0), "r"(a1), "r"(a2), "r"(a3), "r"(b0), "r"(b1));
}
__device__ __forceinline__ float sigf(float z) {
    return 1.0f / (1.0f + __expf(-z));
}
// pack two f32 -> bf16x2 (lo half = a, hi half = b)
__device__ __forceinline__ uint32_t bf16x2_rn(float a, float b) {
    uint32_t r;
    asm("cvt.rn.bf16x2.f32 %0, %1, %2;" : "=r"(r) : "f"(b), "f"(a));
    return r;
}

// ============================================================
// Combo kernel: blocks 0..127 -> vn (32 batches each);
//               blocks 128..159 -> bake fragment-major W_seq table.
// ============================================================
#define VN_SMEM ((16384 + 128 + 8 * 128) * 4)
__global__ __launch_bounds__(256)
void combo_kernel(
    const int*   __restrict__ seq,
    const int*   __restrict__ mask,
    const float* __restrict__ nodes,
    const float* __restrict__ W_last,
    const float* __restrict__ W_seq,
    const float* __restrict__ b_seq,
    float*       __restrict__ out)
{
    extern __shared__ float dsm[];
    const int tid = threadIdx.x, wid = tid >> 5, lane = tid & 31;

    if (blockIdx.x >= 128) {
        // ---- bake g_fragB: one uint4 per thread (4096 total) ----
        const int t = (blockIdx.x - 128) * 256 + tid;
        if (t < 4096) {
            const int p    = t >> 11;            // 0=hi, 1=lo
            const int ks   = (t >> 8) & 7;
            const int wn   = (t >> 5) & 7;
            const int ln   = t & 31;
            const int n0   = wn * 16 + (ln >> 2);
            const int n1   = n0 + 8;
            const int k0   = ks * 16 + 2 * (ln & 3);
            // W row-major [k][n]; fragment wants W^T[n][k] elements
            auto half_of = [&](int k, int n) -> uint32_t {
                const float w = W_seq[k * DD + n];
                const uint32_t bw = __float_as_uint(w);
                if (p == 0) {
                    return bw >> 16;                              // truncated hi as bf16 bits
                } else {
                    const float hi = __uint_as_float(bw & 0xFFFF0000u);
                    return (uint32_t)__bfloat16_as_ushort(__float2bfloat16(w - hi));
                }
            };
            uint4 v;
            v.x = half_of(k0,     n0) | (half_of(k0 + 1, n0) << 16);
            v.y = half_of(k0 + 8, n0) | (half_of(k0 + 9, n0) << 16);
            v.z = half_of(k0,     n1) | (half_of(k0 + 1, n1) << 16);
            v.w = half_of(k0 + 8, n1) | (half_of(k0 + 9, n1) << 16);
            g_fragB[t] = v;
        }
        return;
    }

    // ---- vn: 32 batches per block ----
    float* wl_s = dsm;               // 16384
    float* bs_s = dsm + 16384;       // 128
    float* vnb  = dsm + 16512;       // 8 warps * 128
    const int b0 = blockIdx.x * 32;

    #pragma unroll
    for (int i = tid; i < 4096; i += 256)
        ((float4*)wl_s)[i] = ((const float4*)W_last)[i];
    if (tid < DD) bs_s[tid] = b_seq[tid];
    __syncthreads();

    for (int r = 0; r < 4; r++) {
        const int b = b0 + wid * 4 + r;
        int cnt = ((lane      < LL) ? mask[b * LL + lane]      : 0)
                + ((lane + 32 < LL) ? mask[b * LL + lane + 32] : 0);
        #pragma unroll
        for (int off = 16; off > 0; off >>= 1)
            cnt += __shfl_xor_sync(0xffffffffu, cnt, off);
        int last = 0;
        if (lane == 0)
            last = seq[b * LL + ((cnt > 0) ? cnt - 1 : LL - 1)];
        last = __shfl_sync(0xffffffffu, last, 0);

        const float4 v = ((const float4*)(nodes + (size_t)b * NN * DD + (size_t)last * DD))[lane];
        ((float4*)(out + (size_t)b * DD))[lane] = v;       // v_n output (exact copy)
        ((float4*)(vnb + wid * 128))[lane] = v;
        __syncwarp();

        float a0 = 0.f, a1 = 0.f, a2 = 0.f, a3 = 0.f;
        const float* vr = vnb + wid * 128;
        #pragma unroll 4
        for (int k = 0; k < 128; k++) {
            const float vk = vr[k];
            const float* wr = wl_s + k * 128 + lane;
            a0 = fmaf(vk, wr[0],  a0);
            a1 = fmaf(vk, wr[32], a1);
            a2 = fmaf(vk, wr[64], a2);
            a3 = fmaf(vk, wr[96], a3);
        }
        float* gv = g_vnp + (size_t)b * DD + lane;
        gv[0]  = a0 + bs_s[lane];
        gv[32] = a1 + bs_s[lane + 32];
        gv[64] = a2 + bs_s[lane + 64];
        gv[96] = a3 + bs_s[lane + 96];
        __syncwarp();
    }
}

// ============================================================
// Main: 4 batches/CTA (two A-phases), 512 threads / 16 warps, 2 CTAs/SM.
// M-split: warps 0-7 own m-tiles 0-3, warps 8-15 own m-tiles 4-6.
// B via fragment-major gmem LDG.128 (L1-hot); A via smem ldmatrix.
// ============================================================
__global__ __launch_bounds__(TPB, 2)
void session_mma_kernel(
    const int*   __restrict__ seq,
    const int*   __restrict__ mask,
    const float* __restrict__ nodes,
    const float* __restrict__ W_alpha,
    float*       __restrict__ out)
{
    extern __shared__ char smem[];
    const uint32_t sb = smem_u32(smem);
    const int tid = threadIdx.x, wid = tid >> 5, lane = tid & 31;
    const int b0 = 4 * blockIdx.x;

    int*   cnt_s   = (int*)  (smem + AUX_CNT);
    float* wa_s    = (float*)(smem + AUX_WA);
    float* vnp_s   = (float*)(smem + AUX_VNP);
    float* alpha_s = (float*)(smem + AUX_ALPHA);
    float* part    = (float*)(smem + AUX_PART);

    if (tid < 256) cnt_s[tid] = 0;        // 4*64 ints
    if (tid < 128) wa_s[tid] = W_alpha[tid];
    // vnp for 4 batches (from combo kernel)
    vnp_s[tid] = g_vnp[(size_t)(b0 + (tid >> 7)) * DD + (tid & 127)];
    __syncthreads();

    // masked counts for 4 batches
    if (tid < 4 * LL) {
        const int bl = tid / LL, pos = tid % LL;
        const int g = (b0 + bl) * LL + pos;
        if (mask[g]) atomicAdd(&cnt_s[bl * 64 + seq[g]], 1);
    }
    // zero pad A rows 100..127 once (never overwritten by node conversion)
    for (int i = 1700 + tid; i < TILE4; i += TPB) {
        ((float4*)(smem + A_HI))[i] = make_float4(0.f, 0.f, 0.f, 0.f);
        ((float4*)(smem + A_LO))[i] = make_float4(0.f, 0.f, 0.f, 0.f);
    }

    const int lr  = lane & 7;
    const int g8  = (lane >> 3) & 1;
    const int g16 = lane >> 4;
    const int wn  = wid & 7;              // n-slot: 8 slots x 16 cols
    const int mg  = wid >> 3;             // m-group: 0 -> mt 0..3, 1 -> mt 4..6
    const int mt0 = mg * 4;
    const int mtN = mg ? 3 : 4;
    const int nbase = wn * 16;
    const uint32_t aRow = (uint32_t)(8 * g8 + lr) * (PK * 2) + (uint32_t)g16 * 16;
    const uint4* fbB = g_fragB + wn * 32 + lane;   // + p*2048 + ks*256

    #pragma unroll 1
    for (int ph = 0; ph < 2; ph++) {
        const int pb = b0 + 2 * ph;

        // ---- stage A: nodes (rows 0..99) -> split bf16 (truncation split) ----
        {
            const float4* nv = (const float4*)(nodes + (size_t)pb * NN * DD);
            #pragma unroll 2
            for (int i = tid; i < 3200; i += TPB) {
                const float4 x = nv[i];
                const int e = i * 4, row = e >> 7, k = e & 127;
                const uint32_t bx = __float_as_uint(x.x);
                const uint32_t by = __float_as_uint(x.y);
                const uint32_t bz = __float_as_uint(x.z);
                const uint32_t bw = __float_as_uint(x.w);
                uint2 vh, vl;
                vh.x = __byte_perm(bx, by, 0x7632);   // lo16 = hi(x.x), hi16 = hi(x.y)
                vh.y = __byte_perm(bz, bw, 0x7632);
                const float h0 = __uint_as_float(bx & 0xFFFF0000u);
                const float h1 = __uint_as_float(by & 0xFFFF0000u);
                const float h2 = __uint_as_float(bz & 0xFFFF0000u);
                const float h3 = __uint_as_float(bw & 0xFFFF0000u);
                vl.x = bf16x2_rn(x.x - h0, x.y - h1);
                vl.y = bf16x2_rn(x.z - h2, x.w - h3);
                const uint32_t off = (uint32_t)row * (PK * 2) + (uint32_t)k * 2;  // 8B aligned
                *(uint2*)(smem + A_HI + off) = vh;
                *(uint2*)(smem + A_LO + off) = vl;
            }
        }
        __syncthreads();

        // ---- mma.sync mainloop: <=4 m-tiles x 2 n-tiles per warp, 8 k-steps, 3 passes ----
        float d[4][2][4];
        #pragma unroll
        for (int mt = 0; mt < 4; mt++)
            #pragma unroll
            for (int nt = 0; nt < 2; nt++)
                #pragma unroll
                for (int e = 0; e < 4; e++) d[mt][nt][e] = 0.f;

        #pragma unroll
        for (int pass = 0; pass < 3; pass++) {
            const uint32_t Ab = sb + ((pass == 2) ? A_LO : A_HI) + (uint32_t)mt0 * (16 * PK * 2);
            const uint4* fb = fbB + ((pass == 1) ? 2048 : 0);
            #pragma unroll
            for (int ks = 0; ks < 8; ks++) {
                const uint32_t kb = (uint32_t)ks * 32;   // 16 elems * 2B
                const uint4 w = fb[ks * 256];            // B frags: coalesced LDG.128, L1-hot
                #pragma unroll
                for (int mt = 0; mt < 4; mt++) {
                    if (mt < mtN) {
                        uint32_t a0, a1, a2, a3;
                        ldsm_x4(a0, a1, a2, a3, Ab + aRow + (uint32_t)mt * (16 * PK * 2) + kb);
                        mma_bf16(d[mt][0], a0, a1, a2, a3, w.x, w.y);
                        mma_bf16(d[mt][1], a0, a1, a2, a3, w.z, w.w);
                    }
                }
            }
        }

        // ---- epilogue: sigmoid, scale by W_alpha, row-wise reduce ----
        {
            const int q = lane & 3;
            #pragma unroll
            for (int mt = 0; mt < 4; mt++) {
                if (mt < mtN) {
                    const int r0 = 16 * (mt0 + mt) + (lane >> 2);
                    const int r1 = r0 + 8;
                    const float* vp0 = vnp_s + (2 * ph + ((r0 < 50) ? 0 : 1)) * 128;
                    const float* vp1 = vnp_s + (2 * ph + ((r1 < 50) ? 0 : 1)) * 128;
                    float p0 = 0.f, p1 = 0.f;
                    #pragma unroll
                    for (int nt = 0; nt < 2; nt++) {
                        const int c = nbase + nt * 8 + 2 * q;
                        const float wa0 = wa_s[c], wa1 = wa_s[c + 1];
                        p0 += sigf(vp0[c] + d[mt][nt][0]) * wa0 + sigf(vp0[c + 1] + d[mt][nt][1]) * wa1;
                        p1 += sigf(vp1[c] + d[mt][nt][2]) * wa0 + sigf(vp1[c + 1] + d[mt][nt][3]) * wa1;
                    }
                    p0 += __shfl_xor_sync(0xffffffffu, p0, 1);
                    p0 += __shfl_xor_sync(0xffffffffu, p0, 2);
                    p1 += __shfl_xor_sync(0xffffffffu, p1, 1);
                    p1 += __shfl_xor_sync(0xffffffffu, p1, 2);
                    if ((lane & 3) == 0) {
                        part[r0 * 8 + wn] = p0;
                        part[r1 * 8 + wn] = p1;
                    }
                }
            }
        }
        __syncthreads();

        // alpha[n] (x masked multiplicity), rows 0..99 of this phase
        if (tid < 100) {
            float a = 0.f;
            #pragma unroll
            for (int w = 0; w < 8; w++) a += part[tid * 8 + w];
            const int bt = (tid < 50) ? 0 : 1;
            const int n  = tid - bt * 50;
            const int g  = 2 * ph + bt;
            alpha_s[g * 64 + n] = a * (float)cnt_s[g * 64 + n];
        }
        __syncthreads();
    }

    // ---- session_graph for all 4 batches (nodes re-read, L2-hot) ----
    {
        const int bl = tid >> 7;          // 0..3
        const int c  = tid & 127;
        const int b  = b0 + bl;
        const float* nb = nodes + (size_t)b * NN * DD;
        const float* as = alpha_s + bl * 64;
        float sg = 0.f;
        #pragma unroll
        for (int n = 0; n < NN; n++)
            sg = fmaf(as[n], nb[n * DD + c], sg);
        out[(size_t)BB * DD + (size_t)b * DD + c] = sg;
    }
}

extern "C" void kernel_launch(void* const* d_in, const int* in_sizes, int n_in,
                              void* d_out, int out_size) {
    const int*   seq     = (const int*)  d_in[0];
    const int*   mask    = (const int*)  d_in[1];
    const float* nodes   = (const float*)d_in[2];
    // d_in[3] = batch_size scalar (compile-time constants used)
    const float* W_last  = (const float*)d_in[4];
    const float* W_seq   = (const float*)d_in[5];
    const float* b_seq   = (const float*)d_in[6];
    const float* W_alpha = (const float*)d_in[7];
    float* out = (float*)d_out;

    cudaFuncSetAttribute(combo_kernel, cudaFuncAttributeMaxDynamicSharedMemorySize, VN_SMEM);
    combo_kernel<<<160, 256, VN_SMEM>>>(seq, mask, nodes, W_last, W_seq, b_seq, out);

    cudaFuncSetAttribute(session_mma_kernel,
                         cudaFuncAttributeMaxDynamicSharedMemorySize, SMEM_TOTAL);
    session_mma_kernel<<<1024, TPB, SMEM_TOTAL>>>(seq, mask, nodes, W_alpha, out);
}

// round 16
// speedup vs baseline: 1.4060x; 1.4060x over previous
#include <cuda_runtime.h>
#include <cuda_bf16.h>
#include <cstdint>
#include <cstddef>

#define BB 4096
#define LL 50
#define NN 50
#define DD 128
#define PK 136                    // padded row stride (elements) -> 272B = 17*16: LDSM-aligned, conflict-free
#define TILE4 2176                // float4s per bf16 tile image (128*PK*2/16)
#define TPB 512
#define TILEB 34816               // bytes per A half-tile image

// ---- main-kernel smem layout (byte offsets) ----
// A buffers: buf b at b*2*TILEB (hi), b*2*TILEB+TILEB (lo)
#define AUX   139264
#define AUX_CNT   (AUX + 0)       // int[8][64]   = 2048
#define AUX_WA    (AUX + 2048)    // float[128]   = 512
#define AUX_VNP   (AUX + 2560)    // float[8][128]= 4096
#define AUX_ALPHA (AUX + 6656)    // float[8][64] = 2048
#define AUX_PART  (AUX + 8704)    // float[128][8]= 4096
#define SMEM_TOTAL (AUX + 12800)  // 152064 -> 1 CTA/SM

__device__ float g_vnp[BB * DD];
// Fragment-major B table: idx = p*2048 + ks*256 + wn*32 + lane (p: 0=hi,1=lo)
__device__ __align__(16) uint4 g_fragB[4096];   // 64 KB

__device__ __forceinline__ uint32_t smem_u32(const void* p) {
    uint32_t a;
    asm("{ .reg .u64 t; cvta.to.shared.u64 t, %1; cvt.u32.u64 %0, t; }" : "=r"(a) : "l"(p));
    return a;
}
__device__ __forceinline__ void ldsm_x4(uint32_t& r0, uint32_t& r1, uint32_t& r2, uint32_t& r3, uint32_t addr) {
    asm volatile("ldmatrix.sync.aligned.m8n8.x4.shared.b16 {%0,%1,%2,%3}, [%4];"
                 : "=r"(r0), "=r"(r1), "=r"(r2), "=r"(r3) : "r"(addr));
}
__device__ __forceinline__ void mma_bf16(float* d, uint32_t a0, uint32_t a1, uint32_t a2, uint32_t a3,
                                         uint32_t b0, uint32_t b1) {
    asm volatile("mma.sync.aligned.m16n8k16.row.col.f32.bf16.bf16.f32 "
                 "{%0,%1,%2,%3}, {%4,%5,%6,%7}, {%8,%9}, {%0,%1,%2,%3};"
                 : "+f"(d[0]), "+f"(d[1]), "+f"(d[2]), "+f"(d[3])
                 : "r"(a0), "r"(a1), "r"(a2), "r"(a3), "r"(b0), "r"(b1));
}
__device__ __forceinline__ float sigf(float z) {
    return 1.0f / (1.0f + __expf(-z));
}
__device__ __forceinline__ uint32_t bf16x2_rn(float a, float b) {
    uint32_t r;
    asm("cvt.rn.bf16x2.f32 %0, %1, %2;" : "=r"(r) : "f"(b), "f"(a));
    return r;
}

// ============================================================
// Combo kernel: blocks 0..127 -> vn (32 batches each);
//               blocks 128..159 -> bake fragment-major W_seq table.
// ============================================================
#define VN_SMEM ((16384 + 128 + 8 * 128) * 4)
__global__ __launch_bounds__(256)
void combo_kernel(
    const int*   __restrict__ seq,
    const int*   __restrict__ mask,
    const float* __restrict__ nodes,
    const float* __restrict__ W_last,
    const float* __restrict__ W_seq,
    const float* __restrict__ b_seq,
    float*       __restrict__ out)
{
    extern __shared__ float dsm[];
    const int tid = threadIdx.x, wid = tid >> 5, lane = tid & 31;

    if (blockIdx.x >= 128) {
        // ---- bake g_fragB: one uint4 per thread ----
        const int t = (blockIdx.x - 128) * 256 + tid;
        if (t < 4096) {
            const int p    = t >> 11;            // 0=hi, 1=lo
            const int ks   = (t >> 8) & 7;
            const int wn   = (t >> 5) & 7;
            const int ln   = t & 31;
            const int n0   = wn * 16 + (ln >> 2);
            const int n1   = n0 + 8;
            const int k0   = ks * 16 + 2 * (ln & 3);
            auto half_of = [&](int k, int n) -> uint32_t {
                const float w = W_seq[k * DD + n];
                const uint32_t bw = __float_as_uint(w);
                if (p == 0) {
                    return bw >> 16;                              // truncated hi as bf16 bits
                } else {
                    const float hi = __uint_as_float(bw & 0xFFFF0000u);
                    return (uint32_t)__bfloat16_as_ushort(__float2bfloat16(w - hi));
                }
            };
            uint4 v;
            v.x = half_of(k0,     n0) | (half_of(k0 + 1, n0) << 16);
            v.y = half_of(k0 + 8, n0) | (half_of(k0 + 9, n0) << 16);
            v.z = half_of(k0,     n1) | (half_of(k0 + 1, n1) << 16);
            v.w = half_of(k0 + 8, n1) | (half_of(k0 + 9, n1) << 16);
            g_fragB[t] = v;
        }
        return;
    }

    // ---- vn: 32 batches per block ----
    float* wl_s = dsm;               // 16384
    float* bs_s = dsm + 16384;       // 128
    float* vnb  = dsm + 16512;       // 8 warps * 128
    const int b0 = blockIdx.x * 32;

    #pragma unroll
    for (int i = tid; i < 4096; i += 256)
        ((float4*)wl_s)[i] = ((const float4*)W_last)[i];
    if (tid < DD) bs_s[tid] = b_seq[tid];
    __syncthreads();

    for (int r = 0; r < 4; r++) {
        const int b = b0 + wid * 4 + r;
        int cnt = ((lane      < LL) ? mask[b * LL + lane]      : 0)
                + ((lane + 32 < LL) ? mask[b * LL + lane + 32] : 0);
        #pragma unroll
        for (int off = 16; off > 0; off >>= 1)
            cnt += __shfl_xor_sync(0xffffffffu, cnt, off);
        int last = 0;
        if (lane == 0)
            last = seq[b * LL + ((cnt > 0) ? cnt - 1 : LL - 1)];
        last = __shfl_sync(0xffffffffu, last, 0);

        const float4 v = ((const float4*)(nodes + (size_t)b * NN * DD + (size_t)last * DD))[lane];
        ((float4*)(out + (size_t)b * DD))[lane] = v;       // v_n output (exact copy)
        ((float4*)(vnb + wid * 128))[lane] = v;
        __syncwarp();

        float a0 = 0.f, a1 = 0.f, a2 = 0.f, a3 = 0.f;
        const float* vr = vnb + wid * 128;
        #pragma unroll 4
        for (int k = 0; k < 128; k++) {
            const float vk = vr[k];
            const float* wr = wl_s + k * 128 + lane;
            a0 = fmaf(vk, wr[0],  a0);
            a1 = fmaf(vk, wr[32], a1);
            a2 = fmaf(vk, wr[64], a2);
            a3 = fmaf(vk, wr[96], a3);
        }
        float* gv = g_vnp + (size_t)b * DD + lane;
        gv[0]  = a0 + bs_s[lane];
        gv[32] = a1 + bs_s[lane + 32];
        gv[64] = a2 + bs_s[lane + 64];
        gv[96] = a3 + bs_s[lane + 96];
        __syncwarp();
    }
}

// convert one float4 of node data -> split bf16 pair writes
__device__ __forceinline__ void conv_store(char* smem, int buf, int i, float4 x) {
    const int e = i * 4, row = e >> 7, k = e & 127;
    const uint32_t bx = __float_as_uint(x.x);
    const uint32_t by = __float_as_uint(x.y);
    const uint32_t bz = __float_as_uint(x.z);
    const uint32_t bw = __float_as_uint(x.w);
    uint2 vh, vl;
    vh.x = __byte_perm(bx, by, 0x7632);
    vh.y = __byte_perm(bz, bw, 0x7632);
    const float h0 = __uint_as_float(bx & 0xFFFF0000u);
    const float h1 = __uint_as_float(by & 0xFFFF0000u);
    const float h2 = __uint_as_float(bz & 0xFFFF0000u);
    const float h3 = __uint_as_float(bw & 0xFFFF0000u);
    vl.x = bf16x2_rn(x.x - h0, x.y - h1);
    vl.y = bf16x2_rn(x.z - h2, x.w - h3);
    const uint32_t off = (uint32_t)row * (PK * 2) + (uint32_t)k * 2;   // 8B aligned
    char* base = smem + buf * (2 * TILEB);
    *(uint2*)(base + off) = vh;            // hi
    *(uint2*)(base + TILEB + off) = vl;    // lo
}

// ============================================================
// Main: 8 batches/CTA (4 phases), 512 thr / 16 warps, double-buffered A,
// B via fragment-major gmem table, prefetch-pipelined staging.
// ============================================================
__global__ __launch_bounds__(TPB)
void session_mma_kernel(
    const int*   __restrict__ seq,
    const int*   __restrict__ mask,
    const float* __restrict__ nodes,
    const float* __restrict__ W_alpha,
    float*       __restrict__ out)
{
    extern __shared__ char smem[];
    const uint32_t sb = smem_u32(smem);
    const int tid = threadIdx.x, wid = tid >> 5, lane = tid & 31;
    const int b0 = 8 * blockIdx.x;

    int*   cnt_s   = (int*)  (smem + AUX_CNT);
    float* wa_s    = (float*)(smem + AUX_WA);
    float* vnp_s   = (float*)(smem + AUX_VNP);
    float* alpha_s = (float*)(smem + AUX_ALPHA);
    float* part    = (float*)(smem + AUX_PART);

    cnt_s[tid] = 0;                       // 8*64 = 512 ints
    if (tid < 128) wa_s[tid] = W_alpha[tid];
    // vnp for 8 batches
    #pragma unroll
    for (int j = 0; j < 2; j++) {
        const int i = tid + j * TPB;      // 0..1023
        vnp_s[i] = g_vnp[(size_t)(b0 + (i >> 7)) * DD + (i & 127)];
    }
    // zero pad A rows 100..127 in BOTH buffers (never overwritten later)
    #pragma unroll
    for (int bf = 0; bf < 2; bf++) {
        char* base = smem + bf * (2 * TILEB);
        for (int i = 1700 + tid; i < TILE4; i += TPB) {
            ((float4*)base)[i] = make_float4(0.f, 0.f, 0.f, 0.f);
            ((float4*)(base + TILEB))[i] = make_float4(0.f, 0.f, 0.f, 0.f);
        }
    }
    __syncthreads();   // cnt_s zeroed before atomics

    // masked counts for 8 batches (400 positions)
    if (tid < 8 * LL) {
        const int bl = tid / LL, pos = tid % LL;
        const int g = (b0 + bl) * LL + pos;
        if (mask[g]) atomicAdd(&cnt_s[bl * 64 + seq[g]], 1);
    }

    // ---- stage phase 0 into buffer 0 ----
    {
        const float4* nv = (const float4*)(nodes + (size_t)b0 * NN * DD);
        #pragma unroll
        for (int j = 0; j < 7; j++) {
            const int i = tid + j * TPB;
            if (i < 3200) conv_store(smem, 0, i, nv[i]);
        }
    }
    __syncthreads();

    const int lr  = lane & 7;
    const int g8  = (lane >> 3) & 1;
    const int g16 = lane >> 4;
    const int wn  = wid & 7;              // n-slot: 8 slots x 16 cols
    const int mg  = wid >> 3;             // m-group: 0 -> mt 0..3, 1 -> mt 4..6
    const int mt0 = mg * 4;
    const int mtN = mg ? 3 : 4;
    const int nbase = wn * 16;
    const uint32_t aRow = (uint32_t)(8 * g8 + lr) * (PK * 2) + (uint32_t)g16 * 16;
    const uint4* fbB = g_fragB + wn * 32 + lane;

    #pragma unroll 1
    for (int ph = 0; ph < 4; ph++) {
        const int buf = ph & 1;

        // ---- prefetch next phase's node data into registers (LDG hidden under MMA) ----
        float4 pf[7];
        const bool haveNext = (ph < 3);
        if (haveNext) {
            const float4* nv = (const float4*)(nodes + (size_t)(b0 + 2 * (ph + 1)) * NN * DD);
            #pragma unroll
            for (int j = 0; j < 7; j++) {
                const int i = tid + j * TPB;
                if (i < 3200) pf[j] = nv[i];
            }
        }

        // ---- mma.sync mainloop on buf: <=4 m-tiles x 2 n-tiles, 8 ks, 3 passes ----
        float d[4][2][4];
        #pragma unroll
        for (int mt = 0; mt < 4; mt++)
            #pragma unroll
            for (int nt = 0; nt < 2; nt++)
                #pragma unroll
                for (int e = 0; e < 4; e++) d[mt][nt][e] = 0.f;

        #pragma unroll
        for (int pass = 0; pass < 3; pass++) {
            const uint32_t Ab = sb + (uint32_t)buf * (2 * TILEB)
                              + ((pass == 2) ? (uint32_t)TILEB : 0u)
                              + (uint32_t)mt0 * (16 * PK * 2);
            const uint4* fb = fbB + ((pass == 1) ? 2048 : 0);
            #pragma unroll
            for (int ks = 0; ks < 8; ks++) {
                const uint32_t kb = (uint32_t)ks * 32;
                const uint4 w = fb[ks * 256];        // coalesced LDG.128, L1-hot
                #pragma unroll
                for (int mt = 0; mt < 4; mt++) {
                    if (mt < mtN) {
                        uint32_t a0, a1, a2, a3;
                        ldsm_x4(a0, a1, a2, a3, Ab + aRow + (uint32_t)mt * (16 * PK * 2) + kb);
                        mma_bf16(d[mt][0], a0, a1, a2, a3, w.x, w.y);
                        mma_bf16(d[mt][1], a0, a1, a2, a3, w.z, w.w);
                    }
                }
            }
        }

        // ---- convert + store next phase's A into the other buffer ----
        if (haveNext) {
            #pragma unroll
            for (int j = 0; j < 7; j++) {
                const int i = tid + j * TPB;
                if (i < 3200) conv_store(smem, buf ^ 1, i, pf[j]);
            }
        }

        // ---- epilogue: sigmoid, scale by W_alpha, row-wise reduce ----
        {
            const int q = lane & 3;
            #pragma unroll
            for (int mt = 0; mt < 4; mt++) {
                if (mt < mtN) {
                    const int r0 = 16 * (mt0 + mt) + (lane >> 2);
                    const int r1 = r0 + 8;
                    const float* vp0 = vnp_s + (2 * ph + ((r0 < 50) ? 0 : 1)) * 128;
                    const float* vp1 = vnp_s + (2 * ph + ((r1 < 50) ? 0 : 1)) * 128;
                    float p0 = 0.f, p1 = 0.f;
                    #pragma unroll
                    for (int nt = 0; nt < 2; nt++) {
                        const int c = nbase + nt * 8 + 2 * q;
                        const float wa0 = wa_s[c], wa1 = wa_s[c + 1];
                        p0 += sigf(vp0[c] + d[mt][nt][0]) * wa0 + sigf(vp0[c + 1] + d[mt][nt][1]) * wa1;
                        p1 += sigf(vp1[c] + d[mt][nt][2]) * wa0 + sigf(vp1[c + 1] + d[mt][nt][3]) * wa1;
                    }
                    p0 += __shfl_xor_sync(0xffffffffu, p0, 1);
                    p0 += __shfl_xor_sync(0xffffffffu, p0, 2);
                    p1 += __shfl_xor_sync(0xffffffffu, p1, 1);
                    p1 += __shfl_xor_sync(0xffffffffu, p1, 2);
                    if ((lane & 3) == 0) {
                        part[r0 * 8 + wn] = p0;
                        part[r1 * 8 + wn] = p1;
                    }
                }
            }
        }
        __syncthreads();

        // alpha[n] (x masked multiplicity), rows 0..99 of this phase
        if (tid < 100) {
            float a = 0.f;
            #pragma unroll
            for (int w = 0; w < 8; w++) a += part[tid * 8 + w];
            const int bt = (tid < 50) ? 0 : 1;
            const int n  = tid - bt * 50;
            const int g  = 2 * ph + bt;
            alpha_s[g * 64 + n] = a * (float)cnt_s[g * 64 + n];
        }
        __syncthreads();   // also covers next-buffer A stores before next MMA
    }

    // ---- session_graph for all 8 batches (nodes re-read, L2-hot) ----
    #pragma unroll
    for (int j = 0; j < 2; j++) {
        const int t  = tid + j * TPB;     // 0..1023
        const int bl = t >> 7;            // 0..7
        const int c  = t & 127;
        const int b  = b0 + bl;
        const float* nb = nodes + (size_t)b * NN * DD;
        const float* as = alpha_s + bl * 64;
        float sg = 0.f;
        #pragma unroll
        for (int n = 0; n < NN; n++)
            sg = fmaf(as[n], nb[n * DD + c], sg);
        out[(size_t)BB * DD + (size_t)b * DD + c] = sg;
    }
}

extern "C" void kernel_launch(void* const* d_in, const int* in_sizes, int n_in,
                              void* d_out, int out_size) {
    const int*   seq     = (const int*)  d_in[0];
    const int*   mask    = (const int*)  d_in[1];
    const float* nodes   = (const float*)d_in[2];
    // d_in[3] = batch_size scalar (compile-time constants used)
    const float* W_last  = (const float*)d_in[4];
    const float* W_seq   = (const float*)d_in[5];
    const float* b_seq   = (const float*)d_in[6];
    const float* W_alpha = (const float*)d_in[7];
    float* out = (float*)d_out;

    cudaFuncSetAttribute(combo_kernel, cudaFuncAttributeMaxDynamicSharedMemorySize, VN_SMEM);
    combo_kernel<<<160, 256, VN_SMEM>>>(seq, mask, nodes, W_last, W_seq, b_seq, out);

    cudaFuncSetAttribute(session_mma_kernel,
                         cudaFuncAttributeMaxDynamicSharedMemorySize, SMEM_TOTAL);
    session_mma_kernel<<<512, TPB, SMEM_TOTAL>>>(seq, mask, nodes, W_alpha, out);
}

// round 17
// speedup vs baseline: 1.6328x; 1.1613x over previous
#include <cuda_runtime.h>
#include <cuda_bf16.h>
#include <cstdint>
#include <cstddef>

#define BB 4096
#define LL 50
#define NN 50
#define DD 128
#define PK 136                    // padded row stride (elements) -> 272B = 17*16: LDSM-aligned, conflict-free
#define TILE4 2176                // float4s per bf16 tile image (128*PK*2/16)
#define TPB 512
#define TILEB 34816               // bytes per A tile image (rounded bf16, single image)

// ---- main-kernel smem layout (byte offsets) ----
// A buffers: buf b at b*TILEB
#define AUX   69632
#define AUX_CNT   (AUX + 0)       // int[8][64]   = 2048
#define AUX_WA    (AUX + 2048)    // float[128]   = 512
#define AUX_VNP   (AUX + 2560)    // float[8][128]= 4096
#define AUX_ALPHA (AUX + 6656)    // float[8][64] = 2048
#define AUX_PART  (AUX + 8704)    // float[128][8]= 4096
#define SMEM_TOTAL (AUX + 12800)  // 82432

__device__ float g_vnp[BB * DD];
// Fragment-major B table: idx = p*2048 + ks*256 + wn*32 + lane (p: 0=hi,1=lo; B exact as hi+lo)
__device__ __align__(16) uint4 g_fragB[4096];   // 64 KB

__device__ __forceinline__ uint32_t smem_u32(const void* p) {
    uint32_t a;
    asm("{ .reg .u64 t; cvta.to.shared.u64 t, %1; cvt.u32.u64 %0, t; }" : "=r"(a) : "l"(p));
    return a;
}
__device__ __forceinline__ void ldsm_x4(uint32_t& r0, uint32_t& r1, uint32_t& r2, uint32_t& r3, uint32_t addr) {
    asm volatile("ldmatrix.sync.aligned.m8n8.x4.shared.b16 {%0,%1,%2,%3}, [%4];"
                 : "=r"(r0), "=r"(r1), "=r"(r2), "=r"(r3) : "r"(addr));
}
__device__ __forceinline__ void mma_bf16(float* d, uint32_t a0, uint32_t a1, uint32_t a2, uint32_t a3,
                                         uint32_t b0, uint32_t b1) {
    asm volatile("mma.sync.aligned.m16n8k16.row.col.f32.bf16.bf16.f32 "
                 "{%0,%1,%2,%3}, {%4,%5,%6,%7}, {%8,%9}, {%0,%1,%2,%3};"
                 : "+f"(d[0]), "+f"(d[1]), "+f"(d[2]), "+f"(d[3])
                 : "r"(a0), "r"(a1), "r"(a2), "r"(a3), "r"(b0), "r"(b1));
}
__device__ __forceinline__ float sigf(float z) {
    return 1.0f / (1.0f + __expf(-z));
}
__device__ __forceinline__ uint32_t bf16x2_rn(float a, float b) {
    uint32_t r;
    asm("cvt.rn.bf16x2.f32 %0, %1, %2;" : "=r"(r) : "f"(b), "f"(a));
    return r;
}

// ============================================================
// Combo kernel: blocks 0..127 -> vn (32 batches each);
//               blocks 128..159 -> bake fragment-major W_seq table.
// ============================================================
#define VN_SMEM ((16384 + 128 + 8 * 128) * 4)
__global__ __launch_bounds__(256)
void combo_kernel(
    const int*   __restrict__ seq,
    const int*   __restrict__ mask,
    const float* __restrict__ nodes,
    const float* __restrict__ W_last,
    const float* __restrict__ W_seq,
    const float* __restrict__ b_seq,
    float*       __restrict__ out)
{
    extern __shared__ float dsm[];
    const int tid = threadIdx.x, wid = tid >> 5, lane = tid & 31;

    if (blockIdx.x >= 128) {
        // ---- bake g_fragB: one uint4 per thread ----
        const int t = (blockIdx.x - 128) * 256 + tid;
        if (t < 4096) {
            const int p    = t >> 11;            // 0=hi, 1=lo
            const int ks   = (t >> 8) & 7;
            const int wn   = (t >> 5) & 7;
            const int ln   = t & 31;
            const int n0   = wn * 16 + (ln >> 2);
            const int n1   = n0 + 8;
            const int k0   = ks * 16 + 2 * (ln & 3);
            auto half_of = [&](int k, int n) -> uint32_t {
                const float w = W_seq[k * DD + n];
                const uint32_t bw = __float_as_uint(w);
                if (p == 0) {
                    return bw >> 16;                              // truncated hi as bf16 bits
                } else {
                    const float hi = __uint_as_float(bw & 0xFFFF0000u);
                    return (uint32_t)__bfloat16_as_ushort(__float2bfloat16(w - hi));
                }
            };
            uint4 v;
            v.x = half_of(k0,     n0) | (half_of(k0 + 1, n0) << 16);
            v.y = half_of(k0 + 8, n0) | (half_of(k0 + 9, n0) << 16);
            v.z = half_of(k0,     n1) | (half_of(k0 + 1, n1) << 16);
            v.w = half_of(k0 + 8, n1) | (half_of(k0 + 9, n1) << 16);
            g_fragB[t] = v;
        }
        return;
    }

    // ---- vn: 32 batches per block ----
    float* wl_s = dsm;               // 16384
    float* bs_s = dsm + 16384;       // 128
    float* vnb  = dsm + 16512;       // 8 warps * 128
    const int b0 = blockIdx.x * 32;

    #pragma unroll
    for (int i = tid; i < 4096; i += 256)
        ((float4*)wl_s)[i] = ((const float4*)W_last)[i];
    if (tid < DD) bs_s[tid] = b_seq[tid];
    __syncthreads();

    for (int r = 0; r < 4; r++) {
        const int b = b0 + wid * 4 + r;
        int cnt = ((lane      < LL) ? mask[b * LL + lane]      : 0)
                + ((lane + 32 < LL) ? mask[b * LL + lane + 32] : 0);
        #pragma unroll
        for (int off = 16; off > 0; off >>= 1)
            cnt += __shfl_xor_sync(0xffffffffu, cnt, off);
        int last = 0;
        if (lane == 0)
            last = seq[b * LL + ((cnt > 0) ? cnt - 1 : LL - 1)];
        last = __shfl_sync(0xffffffffu, last, 0);

        const float4 v = ((const float4*)(nodes + (size_t)b * NN * DD + (size_t)last * DD))[lane];
        ((float4*)(out + (size_t)b * DD))[lane] = v;       // v_n output (exact copy)
        ((float4*)(vnb + wid * 128))[lane] = v;
        __syncwarp();

        float a0 = 0.f, a1 = 0.f, a2 = 0.f, a3 = 0.f;
        const float* vr = vnb + wid * 128;
        #pragma unroll 4
        for (int k = 0; k < 128; k++) {
            const float vk = vr[k];
            const float* wr = wl_s + k * 128 + lane;
            a0 = fmaf(vk, wr[0],  a0);
            a1 = fmaf(vk, wr[32], a1);
            a2 = fmaf(vk, wr[64], a2);
            a3 = fmaf(vk, wr[96], a3);
        }
        float* gv = g_vnp + (size_t)b * DD + lane;
        gv[0]  = a0 + bs_s[lane];
        gv[32] = a1 + bs_s[lane + 32];
        gv[64] = a2 + bs_s[lane + 64];
        gv[96] = a3 + bs_s[lane + 96];
        __syncwarp();
    }
}

// convert one float4 of node data -> rounded bf16x4 write
__device__ __forceinline__ void conv_store(char* smem, int buf, int i, float4 x) {
    const int e = i * 4, row = e >> 7, k = e & 127;
    uint2 v;
    v.x = bf16x2_rn(x.x, x.y);
    v.y = bf16x2_rn(x.z, x.w);
    const uint32_t off = (uint32_t)row * (PK * 2) + (uint32_t)k * 2;   // 8B aligned
    *(uint2*)(smem + buf * TILEB + off) = v;
}

// ============================================================
// Main: 8 batches/CTA (4 phases), 512 thr / 16 warps, double-buffered A
// (rounded bf16), B exact-split via fragment-major gmem table, 2 MMA passes.
// ============================================================
__global__ __launch_bounds__(TPB)
void session_mma_kernel(
    const int*   __restrict__ seq,
    const int*   __restrict__ mask,
    const float* __restrict__ nodes,
    const float* __restrict__ W_alpha,
    float*       __restrict__ out)
{
    extern __shared__ char smem[];
    const uint32_t sb = smem_u32(smem);
    const int tid = threadIdx.x, wid = tid >> 5, lane = tid & 31;
    const int b0 = 8 * blockIdx.x;

    int*   cnt_s   = (int*)  (smem + AUX_CNT);
    float* wa_s    = (float*)(smem + AUX_WA);
    float* vnp_s   = (float*)(smem + AUX_VNP);
    float* alpha_s = (float*)(smem + AUX_ALPHA);
    float* part    = (float*)(smem + AUX_PART);

    cnt_s[tid] = 0;                       // 8*64 = 512 ints
    if (tid < 128) wa_s[tid] = W_alpha[tid];
    // vnp for 8 batches
    #pragma unroll
    for (int j = 0; j < 2; j++) {
        const int i = tid + j * TPB;      // 0..1023
        vnp_s[i] = g_vnp[(size_t)(b0 + (i >> 7)) * DD + (i & 127)];
    }
    // zero pad A rows 100..127 in BOTH buffers (never overwritten later)
    #pragma unroll
    for (int bf = 0; bf < 2; bf++) {
        char* base = smem + bf * TILEB;
        for (int i = 1700 + tid; i < TILE4; i += TPB)
            ((float4*)base)[i] = make_float4(0.f, 0.f, 0.f, 0.f);
    }
    __syncthreads();   // cnt_s zeroed before atomics

    // masked counts for 8 batches (400 positions)
    if (tid < 8 * LL) {
        const int bl = tid / LL, pos = tid % LL;
        const int g = (b0 + bl) * LL + pos;
        if (mask[g]) atomicAdd(&cnt_s[bl * 64 + seq[g]], 1);
    }

    // ---- stage phase 0 into buffer 0 ----
    {
        const float4* nv = (const float4*)(nodes + (size_t)b0 * NN * DD);
        #pragma unroll
        for (int j = 0; j < 7; j++) {
            const int i = tid + j * TPB;
            if (i < 3200) conv_store(smem, 0, i, nv[i]);
        }
    }
    __syncthreads();

    const int lr  = lane & 7;
    const int g8  = (lane >> 3) & 1;
    const int g16 = lane >> 4;
    const int wn  = wid & 7;              // n-slot: 8 slots x 16 cols
    const int mg  = wid >> 3;             // m-group: 0 -> mt 0..3, 1 -> mt 4..6
    const int mt0 = mg * 4;
    const int mtN = mg ? 3 : 4;
    const int nbase = wn * 16;
    const uint32_t aRow = (uint32_t)(8 * g8 + lr) * (PK * 2) + (uint32_t)g16 * 16;
    const uint4* fbB = g_fragB + wn * 32 + lane;

    #pragma unroll 1
    for (int ph = 0; ph < 4; ph++) {
        const int buf = ph & 1;

        // ---- prefetch next phase's node data into registers (LDG hidden under MMA) ----
        float4 pf[7];
        const bool haveNext = (ph < 3);
        if (haveNext) {
            const float4* nv = (const float4*)(nodes + (size_t)(b0 + 2 * (ph + 1)) * NN * DD);
            #pragma unroll
            for (int j = 0; j < 7; j++) {
                const int i = tid + j * TPB;
                if (i < 3200) pf[j] = nv[i];
            }
        }

        // ---- mma.sync mainloop on buf: <=4 m-tiles x 2 n-tiles, 8 ks, 2 passes ----
        float d[4][2][4];
        #pragma unroll
        for (int mt = 0; mt < 4; mt++)
            #pragma unroll
            for (int nt = 0; nt < 2; nt++)
                #pragma unroll
                for (int e = 0; e < 4; e++) d[mt][nt][e] = 0.f;

        #pragma unroll
        for (int pass = 0; pass < 2; pass++) {
            const uint32_t Ab = sb + (uint32_t)buf * TILEB + (uint32_t)mt0 * (16 * PK * 2);
            const uint4* fb = fbB + pass * 2048;     // pass0 = B_hi, pass1 = B_lo
            #pragma unroll
            for (int ks = 0; ks < 8; ks++) {
                const uint32_t kb = (uint32_t)ks * 32;
                const uint4 w = fb[ks * 256];        // coalesced LDG.128, L1-hot
                #pragma unroll
                for (int mt = 0; mt < 4; mt++) {
                    if (mt < mtN) {
                        uint32_t a0, a1, a2, a3;
                        ldsm_x4(a0, a1, a2, a3, Ab + aRow + (uint32_t)mt * (16 * PK * 2) + kb);
                        mma_bf16(d[mt][0], a0, a1, a2, a3, w.x, w.y);
                        mma_bf16(d[mt][1], a0, a1, a2, a3, w.z, w.w);
                    }
                }
            }
        }

        // ---- convert + store next phase's A into the other buffer ----
        if (haveNext) {
            #pragma unroll
            for (int j = 0; j < 7; j++) {
                const int i = tid + j * TPB;
                if (i < 3200) conv_store(smem, buf ^ 1, i, pf[j]);
            }
        }

        // ---- epilogue: sigmoid, scale by W_alpha, row-wise reduce ----
        {
            const int q = lane & 3;
            #pragma unroll
            for (int mt = 0; mt < 4; mt++) {
                if (mt < mtN) {
                    const int r0 = 16 * (mt0 + mt) + (lane >> 2);
                    const int r1 = r0 + 8;
                    const float* vp0 = vnp_s + (2 * ph + ((r0 < 50) ? 0 : 1)) * 128;
                    const float* vp1 = vnp_s + (2 * ph + ((r1 < 50) ? 0 : 1)) * 128;
                    float p0 = 0.f, p1 = 0.f;
                    #pragma unroll
                    for (int nt = 0; nt < 2; nt++) {
                        const int c = nbase + nt * 8 + 2 * q;
                        const float wa0 = wa_s[c], wa1 = wa_s[c + 1];
                        p0 += sigf(vp0[c] + d[mt][nt][0]) * wa0 + sigf(vp0[c + 1] + d[mt][nt][1]) * wa1;
                        p1 += sigf(vp1[c] + d[mt][nt][2]) * wa0 + sigf(vp1[c + 1] + d[mt][nt][3]) * wa1;
                    }
                    p0 += __shfl_xor_sync(0xffffffffu, p0, 1);
                    p0 += __shfl_xor_sync(0xffffffffu, p0, 2);
                    p1 += __shfl_xor_sync(0xffffffffu, p1, 1);
                    p1 += __shfl_xor_sync(0xffffffffu, p1, 2);
                    if ((lane & 3) == 0) {
                        part[r0 * 8 + wn] = p0;
                        part[r1 * 8 + wn] = p1;
                    }
                }
            }
        }
        __syncthreads();

        // alpha[n] (x masked multiplicity), rows 0..99 of this phase
        if (tid < 100) {
            float a = 0.f;
            #pragma unroll
            for (int w = 0; w < 8; w++) a += part[tid * 8 + w];
            const int bt = (tid < 50) ? 0 : 1;
            const int n  = tid - bt * 50;
            const int g  = 2 * ph + bt;
            alpha_s[g * 64 + n] = a * (float)cnt_s[g * 64 + n];
        }
        __syncthreads();   // also covers next-buffer A stores before next MMA
    }

    // ---- session_graph for all 8 batches (nodes re-read, L2-hot) ----
    #pragma unroll
    for (int j = 0; j < 2; j++) {
        const int t  = tid + j * TPB;     // 0..1023
        const int bl = t >> 7;            // 0..7
        const int c  = t & 127;
        const int b  = b0 + bl;
        const float* nb = nodes + (size_t)b * NN * DD;
        const float* as = alpha_s + bl * 64;
        float sg = 0.f;
        #pragma unroll
        for (int n = 0; n < NN; n++)
            sg = fmaf(as[n], nb[n * DD + c], sg);
        out[(size_t)BB * DD + (size_t)b * DD + c] = sg;
    }
}

extern "C" void kernel_launch(void* const* d_in, const int* in_sizes, int n_in,
                              void* d_out, int out_size) {
    const int*   seq     = (const int*)  d_in[0];
    const int*   mask    = (const int*)  d_in[1];
    const float* nodes   = (const float*)d_in[2];
    // d_in[3] = batch_size scalar (compile-time constants used)
    const float* W_last  = (const float*)d_in[4];
    const float* W_seq   = (const float*)d_in[5];
    const float* b_seq   = (const float*)d_in[6];
    const float* W_alpha = (const float*)d_in[7];
    float* out = (float*)d_out;

    cudaFuncSetAttribute(combo_kernel, cudaFuncAttributeMaxDynamicSharedMemorySize, VN_SMEM);
    combo_kernel<<<160, 256, VN_SMEM>>>(seq, mask, nodes, W_last, W_seq, b_seq, out);

    cudaFuncSetAttribute(session_mma_kernel,
                         cudaFuncAttributeMaxDynamicSharedMemorySize, SMEM_TOTAL);
    session_mma_kernel<<<512, TPB, SMEM_TOTAL>>>(seq, mask, nodes, W_alpha, out);
}